// round 17
// baseline (speedup 1.0000x reference)
#include <cuda_runtime.h>
#include <cstdint>

// HistPredictor: splat B*K 2D Gaussians onto 128x128 grids, normalize per batch.
// B=256, K=16, grid 128x128 over [-2,2]^2, MIN_SIGMA=0.001.
//
// R17: R11 structure (4 stride-8 chains x 8 steps, scalar f32, 4-CTA cluster,
// DSMEM norm) with second-level geometric seeds: g/V and T/U recurrences cut
// EX2 from 8 to 2 per mixture and trim seed-support ops; last-iteration chain
// multiplies peeled. Threshold -16. Span<=100 warp guard bounds all per-lane
// EX2 args (clamped <=120 for dead lanes; W,U,S <= 1), scalar-EX2 slow path.

#define KMIX 16

__device__ __forceinline__ float ex2f(float x) {
    float r;
    asm("ex2.approx.f32 %0, %1;" : "=f"(r) : "f"(x));
    return r;
}

__global__ __launch_bounds__(128, 8) __cluster_dims__(4, 1, 1)
void gmm_hist_kernel(const float* __restrict__ mu,
                     const float* __restrict__ sigma,
                     const float* __restrict__ cov12,
                     const float* __restrict__ pi,
                     float* __restrict__ out)
{
    // log2-domain coefficients: e = a2*du^2 + b2*du*dv + c2*dv^2 + (lc - lcmax)
    __shared__ float s_a[KMIX], s_b[KMIX], s_c[KMIX], s_c2[KMIX];
    __shared__ float s_mu[KMIX], s_mv[KMIX], s_lc[KMIX];
    __shared__ float s_R[KMIX], s_S[KMIX];
    __shared__ float s_W[KMIX], s_U[KMIX], s_S4[KMIX];  // 2^(2R), 2^(8R), 2^(32R)
    __shared__ float s_red[4];
    __shared__ float s_part[4];

    const int blk = blockIdx.x;
    const int b = blk >> 2;        // batch
    const int q = blk & 3;         // u-quarter == cluster ctarank
    const int t = threadIdx.x;

    const float H   = 4.0f / 127.0f;
    const float L2E = 1.4426950408889634f;

    if (t < KMIX) {
        const int idx = b * KMIX + t;
        float su = fmaxf(sigma[idx * 2 + 0], 0.001f);
        float sv = fmaxf(sigma[idx * 2 + 1], 0.001f);
        float su2 = su * su;
        float sv2 = sv * sv;
        float c11 = su2 + 1e-6f;
        float c22 = sv2 + 1e-6f;
        float off = cov12[idx];
        float det_full = c11 * c22 - off * off;
        // valid = (det_full > 0) & ~isnan(det_full); NaN>0 is false -> covered.
        float ia, ib, ic, det;
        if (det_full > 0.0f) {
            float rdet = 1.0f / det_full;
            ia = c22 * rdet;
            ib = -off * rdet;
            ic = c11 * rdet;
            det = det_full;
        } else {
            ia = 1.0f / su2;
            ib = 0.0f;
            ic = 1.0f / sv2;
            det = su2 * sv2;
        }
        float a2 = -0.5f * L2E * ia;
        float b2 = -L2E * ib;
        float c2 = -0.5f * L2E * ic;   // strictly < 0
        s_a[t]  = a2;
        s_b[t]  = b2;
        s_c[t]  = c2;
        s_c2[t] = 2.0f * c2;
        float R = c2 * (H * H);        // quadratic-in-j coefficient, < 0
        s_R[t]  = R;
        s_S[t]  = -0.5f / R;
        s_W[t]  = ex2f(fmaxf(2.0f  * R, -280.0f));  // <= 1
        s_U[t]  = ex2f(fmaxf(8.0f  * R, -280.0f));  // <= 1
        s_S4[t] = ex2f(fmaxf(32.0f * R, -280.0f));  // <= 1
        s_mu[t] = mu[idx * 2 + 0];
        s_mv[t] = mu[idx * 2 + 1];
        float coef = pi[idx] / (6.283185307179586f * sqrtf(det + 1e-6f));
        s_lc[t]   = __log2f(coef);     // -inf for coef==0
    }
    __syncthreads();

    // rebase by lcmax: exponents <= 0; 2^lcmax cancels in normalization
    float lcmax = s_lc[0];
#pragma unroll
    for (int k = 1; k < KMIX; k++) lcmax = fmaxf(lcmax, s_lc[k]);

    // Thread t owns u = q*32 + (t>>2), v in [(t&3)*32, +32)
    const int u  = q * 32 + (t >> 2);
    const int v0 = (t & 3) * 32;
    const float uc    = -2.0f + (float)u  * H;
    const float vbase = -2.0f + (float)v0 * H;

    float acc[32];
#pragma unroll
    for (int j = 0; j < 32; j++) acc[j] = 0.0f;

#pragma unroll 1
    for (int k = 0; k < KMIX; k++) {
        const float du  = uc    - s_mu[k];
        const float dv0 = vbase - s_mv[k];
        // e(j) = P' + Q*j + R*j^2,  dv = dv0 + j*H,  P' includes lc - lcmax
        const float R = s_R[k];
        const float Q = fmaf(s_c2[k], dv0, s_b[k] * du) * H;
        const float P = fmaf(fmaf(s_b[k], dv0, s_a[k] * du), du,
                             fmaf(s_c[k] * dv0, dv0, s_lc[k] - lcmax));

        // warp-uniform skip: max of concave e over j in [0,31] vs -16
        float jc = fminf(fmaxf(Q * s_S[k], 0.0f), 31.0f);
        float ev = fmaf(jc, fmaf(R, jc, Q), P);
        if (__ballot_sync(0xffffffffu, ev >= -16.0f) == 0u) continue;

        // span test: recurrence path only if every live lane is "shallow".
        // Under span<=100: row min >= -116 (no live-lane underflow), adjacent
        // log2 diffs |Q+R(2j+1)| <= 100 (all ratio exponents representable).
        float e31 = fmaf(31.0f, fmaf(R, 31.0f, Q), P);
        bool lane_steep = (ev >= -16.0f) && ((ev - fminf(P, e31)) > 100.0f);

        if (__any_sync(0xffffffffu, lane_steep)) {
            // ---- slow path (steep/narrow rows): scalar EX2 per point -------
            // unconditionally safe: rebased e <= 0, underflow -> 0
#pragma unroll
            for (int j = 0; j < 32; j++) {
                const float jf = (float)j;
                float e = fmaf(jf, fmaf(R, jf, Q), P);
                acc[j] += ex2f(e);
            }
        } else {
            // ---- fast path: 4 stride-8 chains x 8 steps ---------------------
            // 2 EX2 per mixture; all other seeds via geometric recurrences.
            //   g0 = 2^P ;  V0 = 2^(Q+R) ;  W = 2^(2R) (smem)
            //   g_{c+1} = g_c * V_c ;  V_{c+1} = V_c * W        (c = 0..3)
            //   T0 = 2^(4Q+16R) ;  U = 2^(8R) ;  T_{c+1} = T_c * U
            //   step decay S4 = 2^(32R) (smem)
            // Clamps (<=120) only guard dead lanes (g0 underflowed to exact 0:
            // finite ratios keep them 0); they never bind under the span guard.
            const float W  = s_W[k];
            const float U  = s_U[k];
            const float S4 = s_S4[k];
            float g0 = ex2f(P);
            float V0 = ex2f(fminf(Q + R, 120.0f));
            float g1 = g0 * V0;
            float V1 = V0 * W;
            float g2 = g1 * V1;
            float V2 = V1 * W;
            float g3 = g2 * V2;
            float T0 = ex2f(fminf(fmaf(16.0f, R, 4.0f * Q), 120.0f));
            float T1 = T0 * U;
            float T2 = T1 * U;
            float T3 = T2 * U;
#pragma unroll
            for (int i = 0; i < 8; i++) {
                acc[4 * i + 0] += g0;
                acc[4 * i + 1] += g1;
                acc[4 * i + 2] += g2;
                acc[4 * i + 3] += g3;
                if (i < 7) {                       // peel last-iter updates
                    g0 *= T0;  g1 *= T1;  g2 *= T2;  g3 *= T3;
                    if (i < 6) { T0 *= S4;  T1 *= S4;  T2 *= S4;  T3 *= S4; }
                }
            }
        }
    }

    // CTA partial sum (this u-quarter, rebased domain)
    float s = 0.0f;
#pragma unroll
    for (int j = 0; j < 32; j++) s += acc[j];
#pragma unroll
    for (int o = 16; o > 0; o >>= 1) s += __shfl_xor_sync(0xffffffffu, s, o);
    const int warp = t >> 5;
    const int lane = t & 31;
    if (lane == 0) s_red[warp] = s;
    __syncthreads();

    // Thread 0 scatters this CTA's partial into slot q of all 4 cluster CTAs.
    if (t == 0) {
        float mysum = s_red[0] + s_red[1] + s_red[2] + s_red[3];
        uint32_t laddr;
        asm("{ .reg .u64 tmp; cvta.to.shared.u64 tmp, %1; cvt.u32.u64 %0, tmp; }"
            : "=r"(laddr) : "l"(&s_part[q]));
#pragma unroll
        for (int r = 0; r < 4; r++) {
            uint32_t raddr;
            asm("mapa.shared::cluster.u32 %0, %1, %2;" : "=r"(raddr) : "r"(laddr), "r"(r));
            asm volatile("st.shared::cluster.f32 [%0], %1;" :: "r"(raddr), "f"(mysum)
                         : "memory");
        }
    }
    // Cluster barrier: arrive(release) orders the DSMEM stores; wait(acquire)
    // makes all 4 partials visible in local s_part.
    asm volatile("barrier.cluster.arrive.aligned;" ::: "memory");
    asm volatile("barrier.cluster.wait.aligned;"   ::: "memory");

    const float tot = (s_part[0] + s_part[1]) + (s_part[2] + s_part[3]);
    const float inv = (tot > 0.0f) ? (1.0f / tot) : 1.0f;   // 2^lcmax cancels

    // normalized store (coalesced float4)
    float* op = out + (size_t)b * 16384 + (size_t)u * 128 + v0;
#pragma unroll
    for (int j = 0; j < 32; j += 4) {
        float4 w = make_float4(acc[j] * inv, acc[j + 1] * inv,
                               acc[j + 2] * inv, acc[j + 3] * inv);
        *reinterpret_cast<float4*>(op + j) = w;
    }
}

extern "C" void kernel_launch(void* const* d_in, const int* in_sizes, int n_in,
                              void* d_out, int out_size)
{
    const float* mu    = (const float*)d_in[0];
    const float* sigma = (const float*)d_in[1];
    const float* cov12 = (const float*)d_in[2];
    const float* pi    = (const float*)d_in[3];
    float* out = (float*)d_out;
    gmm_hist_kernel<<<1024, 128>>>(mu, sigma, cov12, pi, out);
}